// round 8
// baseline (speedup 1.0000x reference)
#include <cuda_runtime.h>
#include <cuda_bf16.h>
#include <cstdint>

// Problem constants: N=50000, K=32, D=128, 2D=256
#define D 128
#define TWO_D 256
#define KNBR 32
#define MAX_N 50048

// ---------------------------------------------------------------------------
// Global scratch (no cudaMalloc allowed)
// ---------------------------------------------------------------------------
__device__ float g_wq[(size_t)MAX_N * TWO_D];              // wq = [v|t] @ W.T
// Pre-split W: [khalf][hi=0/lo=1][n*128 + k] bf16 row-major (n = output col)
__device__ __nv_bfloat16 g_Wb[2][2][TWO_D * D];

// ---------------------------------------------------------------------------
// mma.sync helpers (sm_80-class ISA; valid at .target sm_103)
// ---------------------------------------------------------------------------
__device__ __forceinline__ uint32_t smem_u32(const void* p) {
    uint32_t a;
    asm("{ .reg .u64 t; cvta.to.shared.u64 t, %1; cvt.u32.u64 %0, t; }" : "=r"(a) : "l"(p));
    return a;
}
__device__ __forceinline__ void ldsm4(uint32_t& r0, uint32_t& r1, uint32_t& r2, uint32_t& r3,
                                      uint32_t addr) {
    asm volatile("ldmatrix.sync.aligned.m8n8.x4.shared.b16 {%0,%1,%2,%3}, [%4];"
                 : "=r"(r0), "=r"(r1), "=r"(r2), "=r"(r3) : "r"(addr));
}
__device__ __forceinline__ void mma16816(float& c0, float& c1, float& c2, float& c3,
                                         uint32_t a0, uint32_t a1, uint32_t a2, uint32_t a3,
                                         uint32_t b0, uint32_t b1) {
    asm volatile("mma.sync.aligned.m16n8k16.row.col.f32.bf16.bf16.f32 "
                 "{%0,%1,%2,%3}, {%4,%5,%6,%7}, {%8,%9}, {%0,%1,%2,%3};"
                 : "+f"(c0), "+f"(c1), "+f"(c2), "+f"(c3)
                 : "r"(a0), "r"(a1), "r"(a2), "r"(a3), "r"(b0), "r"(b1));
}

// ---------------------------------------------------------------------------
// Kernel 0: split W into hi/lo bf16 images (row-major, per K-half)
// ---------------------------------------------------------------------------
__global__ void prep_w_kernel(const float* __restrict__ W)
{
    int idx = blockIdx.x * blockDim.x + threadIdx.x;   // 0..65535
    if (idx >= TWO_D * TWO_D) return;
    int n  = idx >> 8;
    int kf = idx & 255;
    int kh = kf >> 7;
    int kl = kf & 127;
    float w = W[n * TWO_D + kf];
    __nv_bfloat16 hi = __float2bfloat16(w);
    __nv_bfloat16 lo = __float2bfloat16(w - __bfloat162float(hi));
    g_Wb[kh][0][n * D + kl] = hi;
    g_Wb[kh][1][n * D + kl] = lo;
}

// ---------------------------------------------------------------------------
// Kernel 1: split-bf16 mma.sync GEMM.
// Grid: (ceil(N/64), 2). CTA = 64 rows x 128 cols (blockIdx.y = col half).
// 96 KB smem -> 2 CTAs/SM so one CTA's staging overlaps the other's MMA issue.
// 8 warps in 2(M)x4(N) grid -> 32x32 per warp -> 32 accum regs/thread.
// K=256 as two 128-halves (half0: v_fea x W[:, :128]; half1: t_emb x W[:, 128:]).
// 3 chains per half: Ahi*Bhi + Alo*Bhi + Ahi*Blo, fp32 accumulate in registers.
// Smem: A(64x128) hi/lo + B(128x128) hi/lo bf16, 16B-chunk XOR swizzle
// (phys_chunk = chunk ^ (row & 7)) -> conflict-free ldmatrix.
// ---------------------------------------------------------------------------
#define SM_AHI 0
#define SM_ALO 16384
#define SM_BHI 32768
#define SM_BLO 65536
#define SM_TOTAL 98304   // 96 KB dynamic smem

__global__ __launch_bounds__(256, 2) void gemm_mma_kernel(
    const float* __restrict__ v_fea,
    const float* __restrict__ t_emb,
    float* __restrict__ wq,
    int N)
{
    extern __shared__ char smem[];
    const uint32_t sb = smem_u32(smem);
    const int t = threadIdx.x;       // 0..255
    const int w = t >> 5;            // warp 0..7
    const int l = t & 31;
    const int row0 = blockIdx.x * 64;
    const int cb   = blockIdx.y;          // col half: 0 or 1
    const int warp_m = (w >> 2) * 32;     // 0 or 32
    const int warp_n = (w & 3) * 32;      // 0,32,64,96 (local col)

    float acc[2][4][4];
    #pragma unroll
    for (int i = 0; i < 2; i++)
        #pragma unroll
        for (int j = 0; j < 4; j++)
            #pragma unroll
            for (int q = 0; q < 4; q++)
                acc[i][j][q] = 0.0f;

    // lane-constant ldmatrix address components
    const int arow  = l & 15;            // A: row within 16-row tile
    const int akb   = l >> 4;            // A: k-chunk select (0/1)
    const int arow7 = arow & 7;
    const int brow  = ((l >> 4) << 3) + (l & 7);   // B: n-row within 16
    const int bkb   = (l >> 3) & 1;                // B: k-chunk select
    const int brow7 = l & 7;

    for (int kh = 0; kh < 2; kh++) {
        // ---- stage B: this CTA's 128-col slice of pre-split W (2048 chunks each)
        {
            const uint4* shi = (const uint4*)&g_Wb[kh][0][(size_t)cb * 128 * D];
            const uint4* slo = (const uint4*)&g_Wb[kh][1][(size_t)cb * 128 * D];
            #pragma unroll
            for (int p = 0; p < 8; p++) {
                int idx = p * 256 + t;                 // chunk id 0..2047
                int n = idx >> 4, c = idx & 15;
                uint32_t doff = (uint32_t)(n * 16 + (c ^ (n & 7))) * 16;
                *(uint4*)(smem + SM_BHI + doff) = shi[idx];
                *(uint4*)(smem + SM_BLO + doff) = slo[idx];
            }
        }
        // ---- stage A: fp32 -> hi/lo bf16 convert with swizzle (1024 chunks)
        {
            const float* __restrict__ src = (kh == 0) ? v_fea : t_emb;
            #pragma unroll
            for (int p = 0; p < 4; p++) {
                int idx = p * 256 + t;                 // chunk id 0..1023
                int r = idx >> 4, c = idx & 15;
                int grow = row0 + r;
                float v[8];
                if (grow < N) {
                    const float4 f0 = *(const float4*)(src + (size_t)grow * D + c * 8);
                    const float4 f1 = *(const float4*)(src + (size_t)grow * D + c * 8 + 4);
                    v[0] = f0.x; v[1] = f0.y; v[2] = f0.z; v[3] = f0.w;
                    v[4] = f1.x; v[5] = f1.y; v[6] = f1.z; v[7] = f1.w;
                } else {
                    #pragma unroll
                    for (int q = 0; q < 8; q++) v[q] = 0.0f;
                }
                uint32_t hiw[4], low[4];
                #pragma unroll
                for (int q = 0; q < 4; q++) {
                    __nv_bfloat16 h0 = __float2bfloat16(v[2 * q]);
                    __nv_bfloat16 h1 = __float2bfloat16(v[2 * q + 1]);
                    __nv_bfloat16 l0 = __float2bfloat16(v[2 * q]     - __bfloat162float(h0));
                    __nv_bfloat16 l1 = __float2bfloat16(v[2 * q + 1] - __bfloat162float(h1));
                    hiw[q] = (uint32_t)__bfloat16_as_ushort(h0) | ((uint32_t)__bfloat16_as_ushort(h1) << 16);
                    low[q] = (uint32_t)__bfloat16_as_ushort(l0) | ((uint32_t)__bfloat16_as_ushort(l1) << 16);
                }
                uint32_t doff = (uint32_t)(r * 16 + (c ^ (r & 7))) * 16;
                *(uint4*)(smem + SM_AHI + doff) = make_uint4(hiw[0], hiw[1], hiw[2], hiw[3]);
                *(uint4*)(smem + SM_ALO + doff) = make_uint4(low[0], low[1], low[2], low[3]);
            }
        }
        __syncthreads();

        // ---- compute: 3 chains x 8 k-steps x (2 m-tiles x 2 n-tiles -> 8 mma)
        #pragma unroll
        for (int chain = 0; chain < 3; chain++) {
            const uint32_t Abase = sb + (chain == 1 ? SM_ALO : SM_AHI);
            const uint32_t Bbase = sb + (chain == 2 ? SM_BLO : SM_BHI);
            #pragma unroll
            for (int s = 0; s < 8; s++) {
                uint32_t aF[2][4], bF[2][4];
                #pragma unroll
                for (int i = 0; i < 2; i++) {
                    int rm = warp_m + 16 * i + arow;
                    uint32_t addr = Abase + (uint32_t)rm * 256
                                  + (uint32_t)(((2 * s + akb) ^ arow7) * 16);
                    ldsm4(aF[i][0], aF[i][1], aF[i][2], aF[i][3], addr);
                }
                #pragma unroll
                for (int jj = 0; jj < 2; jj++) {
                    int rn = warp_n + 16 * jj + brow;
                    uint32_t addr = Bbase + (uint32_t)rn * 256
                                  + (uint32_t)(((2 * s + bkb) ^ brow7) * 16);
                    ldsm4(bF[jj][0], bF[jj][1], bF[jj][2], bF[jj][3], addr);
                }
                #pragma unroll
                for (int i = 0; i < 2; i++)
                    #pragma unroll
                    for (int jj = 0; jj < 2; jj++) {
                        mma16816(acc[i][2*jj][0],   acc[i][2*jj][1],   acc[i][2*jj][2],   acc[i][2*jj][3],
                                 aF[i][0], aF[i][1], aF[i][2], aF[i][3], bF[jj][0], bF[jj][1]);
                        mma16816(acc[i][2*jj+1][0], acc[i][2*jj+1][1], acc[i][2*jj+1][2], acc[i][2*jj+1][3],
                                 aF[i][0], aF[i][1], aF[i][2], aF[i][3], bF[jj][2], bF[jj][3]);
                    }
            }
        }
        __syncthreads();
    }

    // ---- epilogue: c fragment (row = l/4, cols 2*(l%4)+{0,1}; +8 rows for c2,c3)
    const int col0 = cb * 128 + warp_n;
    #pragma unroll
    for (int i = 0; i < 2; i++) {
        int ra = row0 + warp_m + 16 * i + (l >> 2);
        #pragma unroll
        for (int j = 0; j < 4; j++) {
            int col = col0 + 8 * j + 2 * (l & 3);
            if (ra < N)
                *(float2*)(wq + (size_t)ra * TWO_D + col) = make_float2(acc[i][j][0], acc[i][j][1]);
            if (ra + 8 < N)
                *(float2*)(wq + (size_t)(ra + 8) * TWO_D + col) = make_float2(acc[i][j][2], acc[i][j][3]);
        }
    }
}

// ---------------------------------------------------------------------------
// Kernel 2: per-node attention, float4-vectorized. (unchanged from R7)
// Block = 1 node, 128 threads (4 warps), each warp owns 8 of 32 neighbors.
// ---------------------------------------------------------------------------
__global__ __launch_bounds__(128) void att_kernel(
    const float* __restrict__ v_fea,
    const float* __restrict__ t_emb,
    const int* __restrict__ ef,
    const float* __restrict__ wq,
    float* __restrict__ out,
    int N)
{
    const int n = blockIdx.x;
    const int t = threadIdx.x;
    const int w = t >> 5;
    const int l = t & 31;

    __shared__ __align__(16) float wqs[TWO_D];
    __shared__ int   efs[KNBR];
    __shared__ float sc[KNBR];
    __shared__ __align__(16) float buf[4][D];

    wqs[t]     = wq[(size_t)n * TWO_D + t];
    wqs[t + D] = wq[(size_t)n * TWO_D + D + t];
    if (t < KNBR) efs[t] = ef[(size_t)n * KNBR + t];
    __syncthreads();

    const float4 wqv = ((const float4*)wqs)[l];
    const float4 wqt = ((const float4*)wqs)[32 + l];

    float4 vv[8];

    #pragma unroll
    for (int kk = 0; kk < 8; kk++) {
        const int k = w * 8 + kk;
        const int e = efs[k];
        const float4 v4 = ((const float4*)(v_fea + (size_t)e * D))[l];
        const float4 t4 = ((const float4*)(t_emb + (size_t)e * D))[l];
        vv[kk] = v4;
        float acc = v4.x * wqv.x + v4.y * wqv.y + v4.z * wqv.z + v4.w * wqv.w
                  + t4.x * wqt.x + t4.y * wqt.y + t4.z * wqt.z + t4.w * wqt.w;
        #pragma unroll
        for (int off = 16; off > 0; off >>= 1)
            acc += __shfl_xor_sync(0xFFFFFFFFu, acc, off);
        if (l == 0) sc[k] = acc;
    }
    __syncthreads();

    if (t < KNBR) {
        float s = sc[t];
        float m = s;
        #pragma unroll
        for (int off = 16; off > 0; off >>= 1)
            m = fmaxf(m, __shfl_xor_sync(0xFFFFFFFFu, m, off));
        float e = __expf(s - m);
        float sum = e;
        #pragma unroll
        for (int off = 16; off > 0; off >>= 1)
            sum += __shfl_xor_sync(0xFFFFFFFFu, sum, off);
        sc[t] = e / sum;
    }
    __syncthreads();

    float4 po = make_float4(0.f, 0.f, 0.f, 0.f);
    #pragma unroll
    for (int kk = 0; kk < 8; kk++) {
        const float r = sc[w * 8 + kk];
        po.x = fmaf(r, vv[kk].x, po.x);
        po.y = fmaf(r, vv[kk].y, po.y);
        po.z = fmaf(r, vv[kk].z, po.z);
        po.w = fmaf(r, vv[kk].w, po.w);
    }
    ((float4*)buf[w])[l] = po;
    __syncthreads();

    if (t < 32) {
        float4 a = ((const float4*)buf[0])[t];
        float4 b = ((const float4*)buf[1])[t];
        float4 c = ((const float4*)buf[2])[t];
        float4 d4 = ((const float4*)buf[3])[t];
        float4 s = make_float4(a.x + b.x + c.x + d4.x, a.y + b.y + c.y + d4.y,
                               a.z + b.z + c.z + d4.z, a.w + b.w + c.w + d4.w);
        ((float4*)out)[(size_t)n * 32 + t] = s;
    }
}

// ---------------------------------------------------------------------------
extern "C" void kernel_launch(void* const* d_in, const int* in_sizes, int n_in,
                              void* d_out, int out_size)
{
    const float* v_fea = (const float*)d_in[0];
    const float* t_emb = (const float*)d_in[1];
    const int*   ef    = (const int*)d_in[2];
    const float* W     = (const float*)d_in[3];
    float*       out   = (float*)d_out;

    const int N = in_sizes[0] / D;

    float* wq;
    cudaGetSymbolAddress((void**)&wq, g_wq);

    cudaFuncSetAttribute(gemm_mma_kernel, cudaFuncAttributeMaxDynamicSharedMemorySize, SM_TOTAL);

    prep_w_kernel<<<256, 256>>>(W);
    dim3 ggrid((N + 63) / 64, 2);
    gemm_mma_kernel<<<ggrid, 256, SM_TOTAL>>>(v_fea, t_emb, wq, N);
    att_kernel<<<N, 128>>>(v_fea, t_emb, ef, wq, out, N);
}

// round 11
// speedup vs baseline: 1.1598x; 1.1598x over previous
#include <cuda_runtime.h>
#include <cuda_bf16.h>
#include <cstdint>

// Problem constants: N=50000, K=32, D=128, 2D=256
#define D 128
#define TWO_D 256
#define KNBR 32
#define MAX_N 50048

// ---------------------------------------------------------------------------
// Global scratch (no cudaMalloc allowed)
// ---------------------------------------------------------------------------
__device__ float g_wq[(size_t)MAX_N * TWO_D];              // wq = [v|t] @ W.T
// Pre-split W: [khalf][hi=0/lo=1][n*128 + k] bf16 row-major (n = output col)
__device__ __nv_bfloat16 g_Wb[2][2][TWO_D * D];

// ---------------------------------------------------------------------------
// mma.sync helpers (sm_80-class ISA; valid at .target sm_103)
// ---------------------------------------------------------------------------
__device__ __forceinline__ uint32_t smem_u32(const void* p) {
    uint32_t a;
    asm("{ .reg .u64 t; cvta.to.shared.u64 t, %1; cvt.u32.u64 %0, t; }" : "=r"(a) : "l"(p));
    return a;
}
__device__ __forceinline__ void ldsm4(uint32_t& r0, uint32_t& r1, uint32_t& r2, uint32_t& r3,
                                      uint32_t addr) {
    asm volatile("ldmatrix.sync.aligned.m8n8.x4.shared.b16 {%0,%1,%2,%3}, [%4];"
                 : "=r"(r0), "=r"(r1), "=r"(r2), "=r"(r3) : "r"(addr));
}
__device__ __forceinline__ void mma16816(float& c0, float& c1, float& c2, float& c3,
                                         uint32_t a0, uint32_t a1, uint32_t a2, uint32_t a3,
                                         uint32_t b0, uint32_t b1) {
    asm volatile("mma.sync.aligned.m16n8k16.row.col.f32.bf16.bf16.f32 "
                 "{%0,%1,%2,%3}, {%4,%5,%6,%7}, {%8,%9}, {%0,%1,%2,%3};"
                 : "+f"(c0), "+f"(c1), "+f"(c2), "+f"(c3)
                 : "r"(a0), "r"(a1), "r"(a2), "r"(a3), "r"(b0), "r"(b1));
}

// ---------------------------------------------------------------------------
// Kernel 0: split W into hi/lo bf16 images (row-major, per K-half)
// ---------------------------------------------------------------------------
__global__ void prep_w_kernel(const float* __restrict__ W)
{
    int idx = blockIdx.x * blockDim.x + threadIdx.x;   // 0..65535
    if (idx >= TWO_D * TWO_D) return;
    int n  = idx >> 8;
    int kf = idx & 255;
    int kh = kf >> 7;
    int kl = kf & 127;
    float w = W[n * TWO_D + kf];
    __nv_bfloat16 hi = __float2bfloat16(w);
    __nv_bfloat16 lo = __float2bfloat16(w - __bfloat162float(hi));
    g_Wb[kh][0][n * D + kl] = hi;
    g_Wb[kh][1][n * D + kl] = lo;
}

// ---------------------------------------------------------------------------
// Kernel 1: split-bf16 mma.sync GEMM (R7 tile shape + fused-chain mainloop).
// CTA = 128 rows x 256 cols. 8 warps in 2(M)x4(N) grid, 64x64 per warp.
// K=256 as two 128-halves (half0: v_fea x W[:, :128]; half1: t_emb x W[:, 128:]).
// Per k-step: load Ahi+Bhi -> 32 mma; load Alo -> 32 mma (Bhi reused);
// load Blo into Alo's regs -> 32 mma (Ahi reused). 16 ldsm + 96 mma per step
// (was 24 + 96). fp32 accumulate in registers.
// Smem: A(128x128) hi/lo + B(256x128) hi/lo bf16 = 192 KB, 16B-chunk XOR
// swizzle (phys_chunk = chunk ^ (row & 7)) -> conflict-free ldmatrix.
// ---------------------------------------------------------------------------
#define SM_AHI 0
#define SM_ALO 32768
#define SM_BHI 65536
#define SM_BLO 131072
#define SM_TOTAL 196608   // 192 KB dynamic smem

__global__ __launch_bounds__(256) void gemm_mma_kernel(
    const float* __restrict__ v_fea,
    const float* __restrict__ t_emb,
    float* __restrict__ wq,
    int N)
{
    extern __shared__ char smem[];
    const uint32_t sb = smem_u32(smem);
    const int t = threadIdx.x;       // 0..255
    const int w = t >> 5;            // warp 0..7
    const int l = t & 31;
    const int row0 = blockIdx.x * 128;
    const int warp_m = (w >> 2) * 64;     // 0 or 64
    const int warp_n = (w & 3) * 64;      // 0,64,128,192

    float acc[4][8][4];
    #pragma unroll
    for (int i = 0; i < 4; i++)
        #pragma unroll
        for (int j = 0; j < 8; j++)
            #pragma unroll
            for (int q = 0; q < 4; q++)
                acc[i][j][q] = 0.0f;

    // lane-constant ldmatrix address components
    const int arow  = l & 15;            // A: row within 16-row tile
    const int akb   = l >> 4;            // A: k-chunk select (0/1)
    const int arow7 = arow & 7;
    const int brow  = ((l >> 4) << 3) + (l & 7);   // B: n-row within 16
    const int bkb   = (l >> 3) & 1;                // B: k-chunk select
    const int brow7 = l & 7;

    for (int kh = 0; kh < 2; kh++) {
        // ---- stage B: copy pre-split bf16 images with swizzle (4096 chunks each)
        {
            const uint4* shi = (const uint4*)g_Wb[kh][0];
            const uint4* slo = (const uint4*)g_Wb[kh][1];
            #pragma unroll
            for (int p = 0; p < 16; p++) {
                int idx = p * 256 + t;                 // chunk id 0..4095
                int n = idx >> 4, c = idx & 15;
                uint32_t doff = (uint32_t)(n * 16 + (c ^ (n & 7))) * 16;
                *(uint4*)(smem + SM_BHI + doff) = shi[idx];
                *(uint4*)(smem + SM_BLO + doff) = slo[idx];
            }
        }
        // ---- stage A: fp32 -> hi/lo bf16 convert with swizzle (2048 chunks)
        {
            const float* __restrict__ src = (kh == 0) ? v_fea : t_emb;
            #pragma unroll
            for (int p = 0; p < 8; p++) {
                int idx = p * 256 + t;                 // chunk id 0..2047
                int r = idx >> 4, c = idx & 15;
                int grow = row0 + r;
                float v[8];
                if (grow < N) {
                    const float4 f0 = *(const float4*)(src + (size_t)grow * D + c * 8);
                    const float4 f1 = *(const float4*)(src + (size_t)grow * D + c * 8 + 4);
                    v[0] = f0.x; v[1] = f0.y; v[2] = f0.z; v[3] = f0.w;
                    v[4] = f1.x; v[5] = f1.y; v[6] = f1.z; v[7] = f1.w;
                } else {
                    #pragma unroll
                    for (int q = 0; q < 8; q++) v[q] = 0.0f;
                }
                uint32_t hiw[4], low[4];
                #pragma unroll
                for (int q = 0; q < 4; q++) {
                    __nv_bfloat16 h0 = __float2bfloat16(v[2 * q]);
                    __nv_bfloat16 h1 = __float2bfloat16(v[2 * q + 1]);
                    __nv_bfloat16 l0 = __float2bfloat16(v[2 * q]     - __bfloat162float(h0));
                    __nv_bfloat16 l1 = __float2bfloat16(v[2 * q + 1] - __bfloat162float(h1));
                    hiw[q] = (uint32_t)__bfloat16_as_ushort(h0) | ((uint32_t)__bfloat16_as_ushort(h1) << 16);
                    low[q] = (uint32_t)__bfloat16_as_ushort(l0) | ((uint32_t)__bfloat16_as_ushort(l1) << 16);
                }
                uint32_t doff = (uint32_t)(r * 16 + (c ^ (r & 7))) * 16;
                *(uint4*)(smem + SM_AHI + doff) = make_uint4(hiw[0], hiw[1], hiw[2], hiw[3]);
                *(uint4*)(smem + SM_ALO + doff) = make_uint4(low[0], low[1], low[2], low[3]);
            }
        }
        __syncthreads();

        // ---- compute: 8 k-steps; per step 3 fused chains with fragment reuse
        #pragma unroll
        for (int s = 0; s < 8; s++) {
            const uint32_t koff_a = (uint32_t)(2 * s + akb);
            const uint32_t koff_b = (uint32_t)(2 * s + bkb);
            uint32_t aH[4][4], bH[4][4], cF[4][4];

            // load Ahi + Bhi
            #pragma unroll
            for (int i = 0; i < 4; i++) {
                int rm = warp_m + 16 * i + arow;
                uint32_t addr = sb + SM_AHI + (uint32_t)rm * 256
                              + (uint32_t)((koff_a ^ arow7) * 16);
                ldsm4(aH[i][0], aH[i][1], aH[i][2], aH[i][3], addr);
            }
            #pragma unroll
            for (int jj = 0; jj < 4; jj++) {
                int rn = warp_n + 16 * jj + brow;
                uint32_t addr = sb + SM_BHI + (uint32_t)rn * 256
                              + (uint32_t)((koff_b ^ brow7) * 16);
                ldsm4(bH[jj][0], bH[jj][1], bH[jj][2], bH[jj][3], addr);
            }
            // chain 0: Ahi x Bhi
            #pragma unroll
            for (int i = 0; i < 4; i++)
                #pragma unroll
                for (int jj = 0; jj < 4; jj++) {
                    mma16816(acc[i][2*jj][0],   acc[i][2*jj][1],   acc[i][2*jj][2],   acc[i][2*jj][3],
                             aH[i][0], aH[i][1], aH[i][2], aH[i][3], bH[jj][0], bH[jj][1]);
                    mma16816(acc[i][2*jj+1][0], acc[i][2*jj+1][1], acc[i][2*jj+1][2], acc[i][2*jj+1][3],
                             aH[i][0], aH[i][1], aH[i][2], aH[i][3], bH[jj][2], bH[jj][3]);
                }
            // load Alo into cF; chain 1: Alo x Bhi (Bhi reused)
            #pragma unroll
            for (int i = 0; i < 4; i++) {
                int rm = warp_m + 16 * i + arow;
                uint32_t addr = sb + SM_ALO + (uint32_t)rm * 256
                              + (uint32_t)((koff_a ^ arow7) * 16);
                ldsm4(cF[i][0], cF[i][1], cF[i][2], cF[i][3], addr);
            }
            #pragma unroll
            for (int i = 0; i < 4; i++)
                #pragma unroll
                for (int jj = 0; jj < 4; jj++) {
                    mma16816(acc[i][2*jj][0],   acc[i][2*jj][1],   acc[i][2*jj][2],   acc[i][2*jj][3],
                             cF[i][0], cF[i][1], cF[i][2], cF[i][3], bH[jj][0], bH[jj][1]);
                    mma16816(acc[i][2*jj+1][0], acc[i][2*jj+1][1], acc[i][2*jj+1][2], acc[i][2*jj+1][3],
                             cF[i][0], cF[i][1], cF[i][2], cF[i][3], bH[jj][2], bH[jj][3]);
                }
            // load Blo into cF; chain 2: Ahi x Blo (Ahi reused)
            #pragma unroll
            for (int jj = 0; jj < 4; jj++) {
                int rn = warp_n + 16 * jj + brow;
                uint32_t addr = sb + SM_BLO + (uint32_t)rn * 256
                              + (uint32_t)((koff_b ^ brow7) * 16);
                ldsm4(cF[jj][0], cF[jj][1], cF[jj][2], cF[jj][3], addr);
            }
            #pragma unroll
            for (int i = 0; i < 4; i++)
                #pragma unroll
                for (int jj = 0; jj < 4; jj++) {
                    mma16816(acc[i][2*jj][0],   acc[i][2*jj][1],   acc[i][2*jj][2],   acc[i][2*jj][3],
                             aH[i][0], aH[i][1], aH[i][2], aH[i][3], cF[jj][0], cF[jj][1]);
                    mma16816(acc[i][2*jj+1][0], acc[i][2*jj+1][1], acc[i][2*jj+1][2], acc[i][2*jj+1][3],
                             aH[i][0], aH[i][1], aH[i][2], aH[i][3], cF[jj][2], cF[jj][3]);
                }
        }
        __syncthreads();
    }

    // ---- epilogue: c fragment (row = l/4, cols 2*(l%4)+{0,1}; +8 rows for c2,c3)
    #pragma unroll
    for (int i = 0; i < 4; i++) {
        int ra = row0 + warp_m + 16 * i + (l >> 2);
        #pragma unroll
        for (int j = 0; j < 8; j++) {
            int col = warp_n + 8 * j + 2 * (l & 3);
            if (ra < N)
                *(float2*)(wq + (size_t)ra * TWO_D + col) = make_float2(acc[i][j][0], acc[i][j][1]);
            if (ra + 8 < N)
                *(float2*)(wq + (size_t)(ra + 8) * TWO_D + col) = make_float2(acc[i][j][2], acc[i][j][3]);
        }
    }
}

// ---------------------------------------------------------------------------
// Kernel 2: per-node attention, float4-vectorized. (unchanged)
// Block = 1 node, 128 threads (4 warps), each warp owns 8 of 32 neighbors.
// ---------------------------------------------------------------------------
__global__ __launch_bounds__(128) void att_kernel(
    const float* __restrict__ v_fea,
    const float* __restrict__ t_emb,
    const int* __restrict__ ef,
    const float* __restrict__ wq,
    float* __restrict__ out,
    int N)
{
    const int n = blockIdx.x;
    const int t = threadIdx.x;
    const int w = t >> 5;
    const int l = t & 31;

    __shared__ __align__(16) float wqs[TWO_D];
    __shared__ int   efs[KNBR];
    __shared__ float sc[KNBR];
    __shared__ __align__(16) float buf[4][D];

    wqs[t]     = wq[(size_t)n * TWO_D + t];
    wqs[t + D] = wq[(size_t)n * TWO_D + D + t];
    if (t < KNBR) efs[t] = ef[(size_t)n * KNBR + t];
    __syncthreads();

    const float4 wqv = ((const float4*)wqs)[l];
    const float4 wqt = ((const float4*)wqs)[32 + l];

    float4 vv[8];

    #pragma unroll
    for (int kk = 0; kk < 8; kk++) {
        const int k = w * 8 + kk;
        const int e = efs[k];
        const float4 v4 = ((const float4*)(v_fea + (size_t)e * D))[l];
        const float4 t4 = ((const float4*)(t_emb + (size_t)e * D))[l];
        vv[kk] = v4;
        float acc = v4.x * wqv.x + v4.y * wqv.y + v4.z * wqv.z + v4.w * wqv.w
                  + t4.x * wqt.x + t4.y * wqt.y + t4.z * wqt.z + t4.w * wqt.w;
        #pragma unroll
        for (int off = 16; off > 0; off >>= 1)
            acc += __shfl_xor_sync(0xFFFFFFFFu, acc, off);
        if (l == 0) sc[k] = acc;
    }
    __syncthreads();

    if (t < KNBR) {
        float s = sc[t];
        float m = s;
        #pragma unroll
        for (int off = 16; off > 0; off >>= 1)
            m = fmaxf(m, __shfl_xor_sync(0xFFFFFFFFu, m, off));
        float e = __expf(s - m);
        float sum = e;
        #pragma unroll
        for (int off = 16; off > 0; off >>= 1)
            sum += __shfl_xor_sync(0xFFFFFFFFu, sum, off);
        sc[t] = e / sum;
    }
    __syncthreads();

    float4 po = make_float4(0.f, 0.f, 0.f, 0.f);
    #pragma unroll
    for (int kk = 0; kk < 8; kk++) {
        const float r = sc[w * 8 + kk];
        po.x = fmaf(r, vv[kk].x, po.x);
        po.y = fmaf(r, vv[kk].y, po.y);
        po.z = fmaf(r, vv[kk].z, po.z);
        po.w = fmaf(r, vv[kk].w, po.w);
    }
    ((float4*)buf[w])[l] = po;
    __syncthreads();

    if (t < 32) {
        float4 a = ((const float4*)buf[0])[t];
        float4 b = ((const float4*)buf[1])[t];
        float4 c = ((const float4*)buf[2])[t];
        float4 d4 = ((const float4*)buf[3])[t];
        float4 s = make_float4(a.x + b.x + c.x + d4.x, a.y + b.y + c.y + d4.y,
                               a.z + b.z + c.z + d4.z, a.w + b.w + c.w + d4.w);
        ((float4*)out)[(size_t)n * 32 + t] = s;
    }
}

// ---------------------------------------------------------------------------
extern "C" void kernel_launch(void* const* d_in, const int* in_sizes, int n_in,
                              void* d_out, int out_size)
{
    const float* v_fea = (const float*)d_in[0];
    const float* t_emb = (const float*)d_in[1];
    const int*   ef    = (const int*)d_in[2];
    const float* W     = (const float*)d_in[3];
    float*       out   = (float*)d_out;

    const int N = in_sizes[0] / D;

    float* wq;
    cudaGetSymbolAddress((void**)&wq, g_wq);

    cudaFuncSetAttribute(gemm_mma_kernel, cudaFuncAttributeMaxDynamicSharedMemorySize, SM_TOTAL);

    prep_w_kernel<<<256, 256>>>(W);
    gemm_mma_kernel<<<(N + 127) / 128, 256, SM_TOTAL>>>(v_fea, t_emb, wq, N);
    att_kernel<<<N, 128>>>(v_fea, t_emb, ef, wq, out, N);
}